// round 8
// baseline (speedup 1.0000x reference)
#include <cuda_runtime.h>
#include <cuda_bf16.h>
#include <cstdint>

#define NUM_K   2048
#define DIMS    256
#define NROWS   16384
#define Q_ELEMS (16 * 256 * 1024)
#define NC      8
#define FLAGMARGIN 2e-3f

// ---- device scratch (no allocation allowed) ----
__device__ __nv_bfloat16 g_cbb[NUM_K * DIMS];   // bf16 codebook [k][d]
__device__ float  g_c2[NUM_K];
__device__ int    g_cand[NROWS * NC];
__device__ unsigned char g_flag[NROWS];
__device__ double g_partial[128];

// ---- gemm smem layout (bytes) ----
#define SM_C2    0          // 2048 floats = 8192
#define SM_ZS    8192       // 128 x 264 bf16 = 67584
#define SM_CB0   75776      // 67584
#define SM_CB1   143360     // 67584
#define SMEM_GEMM 210944
#define ZPITCH   264        // bf16 elems per row (row stride 528B, %128==16)
#define ZPITCHB  528
// merge scratch overlays CB0: mv[32][128] floats, mi[32][128] ints
#define SM_MV    SM_CB0
#define SM_MI    (SM_CB0 + 16384)

// ---- rescore smem layout ----
#define RPITCH   260
#define ROFF_Z2  133120
#define ROFF_IDX 133632
#define ROFF_LR  134144
#define SMEM_RES 134208

// ============================ PTX helpers ============================
__device__ __forceinline__ uint32_t smem_u32(const void* p) {
    uint32_t a;
    asm("{ .reg .u64 t; cvta.to.shared.u64 t, %1; cvt.u32.u64 %0, t; }"
        : "=r"(a) : "l"(p));
    return a;
}
#define CP_ASYNC16(dst, src) \
    asm volatile("cp.async.cg.shared.global [%0], [%1], 16;" \
                 :: "r"(dst), "l"(src) : "memory")
#define CP_COMMIT() asm volatile("cp.async.commit_group;" ::: "memory")
#define CP_WAIT(n)  asm volatile("cp.async.wait_group %0;" :: "n"(n) : "memory")

// non-transposed ldmatrix: codebook [n][k] row-major == col-major B for row.col
#define LDSM_X4(r0, r1, r2, r3, addr) \
    asm volatile("ldmatrix.sync.aligned.m8n8.x4.shared.b16 {%0,%1,%2,%3}, [%4];" \
                 : "=r"(r0), "=r"(r1), "=r"(r2), "=r"(r3) : "r"(addr))

#define MMA16816(c, a0, a1, a2, a3, b0, b1) \
    asm volatile("mma.sync.aligned.m16n8k16.row.col.f32.bf16.bf16.f32 " \
                 "{%0,%1,%2,%3}, {%4,%5,%6,%7}, {%8,%9}, {%0,%1,%2,%3};" \
                 : "+f"((c)[0]), "+f"((c)[1]), "+f"((c)[2]), "+f"((c)[3]) \
                 : "r"(a0), "r"(a1), "r"(a2), "r"(a3), "r"(b0), "r"(b1))

// top-8 ranked insert (registers, fully unrolled / predicated)
__device__ __forceinline__ void ins8(float* cv, int* ci, float p, int j) {
    if (p < cv[NC - 1]) {
        int pos = 0;
#pragma unroll
        for (int q = 0; q < NC; ++q) pos += (cv[q] <= p);
#pragma unroll
        for (int q = NC - 1; q >= 1; --q)
            if (q > pos) { cv[q] = cv[q - 1]; ci[q] = ci[q - 1]; }
#pragma unroll
        for (int q = 0; q < NC; ++q) {
            cv[q] = (q == pos) ? p : cv[q];
            ci[q] = (q == pos) ? j : ci[q];
        }
    }
}

// ============================================================================
// Kernel 1: exact c2 + bf16 codebook
// ============================================================================
__global__ void vq_prep(const float* __restrict__ cb) {
    int wp = threadIdx.x >> 5, lane = threadIdx.x & 31;
    int row = blockIdx.x * 8 + wp;
    float s = 0.f;
#pragma unroll
    for (int q = 0; q < 8; ++q) {
        float v = cb[(size_t)row * DIMS + lane + q * 32];
        g_cbb[(size_t)row * DIMS + lane + q * 32] = __float2bfloat16(v);
        s = __fadd_rn(s, __fmul_rn(v, v));
    }
#pragma unroll
    for (int o = 16; o > 0; o >>= 1)
        s += __shfl_down_sync(0xffffffffu, s, o);
    if (lane == 0) g_c2[row] = s;
}

// ============================================================================
// Kernel 2: bf16 HMMA proxy GEMM -> per-row top-8 candidates + flag
// ============================================================================
__global__ void __launch_bounds__(256, 1)
vq_gemm(const float* __restrict__ z)
{
    extern __shared__ char sm[];
    float* c2s = reinterpret_cast<float*>(sm + SM_C2);
    __nv_bfloat16* Zs = reinterpret_cast<__nv_bfloat16*>(sm + SM_ZS);
    const uint32_t sb = smem_u32(sm);
    const int tid = threadIdx.x, w = tid >> 5, lane = tid & 31;
    const int g = lane >> 2, tig = lane & 3;
    const int n0 = blockIdx.x * 128;
    const float* zb = z + (size_t)(n0 >> 10) * 262144 + (n0 & 1023);

    // prefetch codebook chunk 0 immediately
    const uint32_t cb0 = sb + SM_CB0, cb1 = sb + SM_CB1;
    for (int i = tid; i < 4096; i += 256) {
        int row = i >> 5, seg = i & 31;
        CP_ASYNC16(cb0 + row * ZPITCHB + seg * 16,
                   g_cbb + (size_t)row * 256 + seg * 8);
    }
    CP_COMMIT();

    for (int i = tid; i < 2048; i += 256) c2s[i] = g_c2[i];

    // z tile -> bf16 smem [row][d]
    for (int i = tid; i < 8192; i += 256) {
        int d = i >> 5, r4 = i & 31;
        float4 v = *reinterpret_cast<const float4*>(zb + (size_t)d * 1024 + r4 * 4);
        Zs[(r4 * 4 + 0) * ZPITCH + d] = __float2bfloat16(v.x);
        Zs[(r4 * 4 + 1) * ZPITCH + d] = __float2bfloat16(v.y);
        Zs[(r4 * 4 + 2) * ZPITCH + d] = __float2bfloat16(v.z);
        Zs[(r4 * 4 + 3) * ZPITCH + d] = __float2bfloat16(v.w);
    }

    // per-thread ldmatrix base addresses
    // A (x4): lanes 0-15 -> rows 0-15 @k0 (frags a0/a1), lanes 16-31 -> @k8 (a2/a3)
    const uint32_t a_base = sb + SM_ZS +
        ((w * 16 + (lane & 15)) * ZPITCH + (lane >> 4) * 8) * 2;
    // B (x4, NON-trans): lanes 0-7 n0-7@k0, 8-15 n0-7@k8, 16-23 n8-15@k0, 24-31 n8-15@k8
    const uint32_t b_roff = ((lane & 7) + ((lane >> 4) << 3)) * ZPITCHB +
                            (((lane >> 3) & 1) * 8) * 2;

    float cv0[NC], cv1[NC]; int ci0[NC], ci1[NC];
#pragma unroll
    for (int q = 0; q < NC; ++q) {
        cv0[q] = 3.4e38f; cv1[q] = 3.4e38f; ci0[q] = 0; ci1[q] = 0;
    }

    for (int t = 0; t < 16; ++t) {
        const uint32_t cbuf = (t & 1) ? cb1 : cb0;
        if (t < 15) {
            const uint32_t dst = (t & 1) ? cb0 : cb1;
            const __nv_bfloat16* src = g_cbb + (size_t)(t + 1) * 128 * 256;
            for (int i = tid; i < 4096; i += 256) {
                int row = i >> 5, seg = i & 31;
                CP_ASYNC16(dst + row * ZPITCHB + seg * 16,
                           src + (size_t)row * 256 + seg * 8);
            }
            CP_COMMIT();
            CP_WAIT(1);
        } else {
            CP_WAIT(0);
        }
        __syncthreads();

        float acc[16][4];
#pragma unroll
        for (int nt = 0; nt < 16; ++nt)
#pragma unroll
            for (int q = 0; q < 4; ++q) acc[nt][q] = 0.f;

        const uint32_t b_base = cbuf + b_roff;
#pragma unroll 2
        for (int k16 = 0; k16 < 16; ++k16) {
            uint32_t a0, a1, a2, a3;
            LDSM_X4(a0, a1, a2, a3, a_base + k16 * 32);
#pragma unroll
            for (int nt2 = 0; nt2 < 8; ++nt2) {
                uint32_t b0, b1, b2, b3;
                LDSM_X4(b0, b1, b2, b3,
                        b_base + nt2 * 16 * ZPITCHB + k16 * 32);
                MMA16816(acc[2 * nt2],     a0, a1, a2, a3, b0, b1);
                MMA16816(acc[2 * nt2 + 1], a0, a1, a2, a3, b2, b3);
            }
        }

        // proxies p = c2 - 2*dot, per-thread top-8 update
#pragma unroll
        for (int nt = 0; nt < 16; ++nt) {
            const int jc = t * 128 + nt * 8 + 2 * tig;
            const float c2a = c2s[jc], c2b = c2s[jc + 1];
            ins8(cv0, ci0, __fmaf_rn(-2.f, acc[nt][0], c2a), jc);
            ins8(cv0, ci0, __fmaf_rn(-2.f, acc[nt][1], c2b), jc + 1);
            ins8(cv1, ci1, __fmaf_rn(-2.f, acc[nt][2], c2a), jc);
            ins8(cv1, ci1, __fmaf_rn(-2.f, acc[nt][3], c2b), jc + 1);
        }
        __syncthreads();
    }

    // ---- merge 4 threads x top-8 per row via smem (overlay CB0) ----
    float* mv = reinterpret_cast<float*>(sm + SM_MV);   // [32][128]
    int*   mi = reinterpret_cast<int*>(sm + SM_MI);     // [32][128]
    const int r0 = w * 16 + g, r1 = r0 + 8;
#pragma unroll
    for (int q = 0; q < NC; ++q) {
        mv[(tig * 8 + q) * 128 + r0] = cv0[q]; mi[(tig * 8 + q) * 128 + r0] = ci0[q];
        mv[(tig * 8 + q) * 128 + r1] = cv1[q]; mi[(tig * 8 + q) * 128 + r1] = ci1[q];
    }
    __syncthreads();
    if (tid < 128) {
        float v0 = 0.f, v7 = 0.f;
#pragma unroll
        for (int s = 0; s < NC; ++s) {
            int bm = s;
            float bv = mv[s * 128 + tid];
            for (int q = s + 1; q < 32; ++q) {
                float x = mv[q * 128 + tid];
                if (x < bv) { bv = x; bm = q; }
            }
            float tv = mv[s * 128 + tid]; int ti = mi[s * 128 + tid];
            int bi = mi[bm * 128 + tid];
            mv[s * 128 + tid] = bv;  mi[s * 128 + tid] = bi;
            mv[bm * 128 + tid] = tv; mi[bm * 128 + tid] = ti;
            g_cand[(n0 + tid) * NC + s] = bi;
            if (s == 0) v0 = bv;
            if (s == NC - 1) v7 = bv;
        }
        g_flag[n0 + tid] = (v7 < v0 + FLAGMARGIN) ? 1 : 0;
    }
}

// ============================================================================
// Kernel 3: exact fp32 rescore + fused output/loss (Round-4 math)
// ============================================================================
__global__ void __launch_bounds__(256, 1)
vq_rescore(const float* __restrict__ z, const float* __restrict__ cb,
           float* __restrict__ out)
{
    extern __shared__ char sm[];
    float*  Zs   = reinterpret_cast<float*>(sm);             // [128][260]
    float*  z2s  = reinterpret_cast<float*>(sm + ROFF_Z2);
    int*    idxs = reinterpret_cast<int*>(sm + ROFF_IDX);
    double* lred = reinterpret_cast<double*>(sm + ROFF_LR);
    const int tid = threadIdx.x, w = tid >> 5, lane = tid & 31;
    const int n0 = blockIdx.x * 128;
    const float* zb   = z   + (size_t)(n0 >> 10) * 262144 + (n0 & 1023);
    float*       outb = out + (size_t)(n0 >> 10) * 262144 + (n0 & 1023);

    for (int i = tid; i < 8192; i += 256) {
        int d = i >> 5, r4 = i & 31;
        float4 v = *reinterpret_cast<const float4*>(zb + (size_t)d * 1024 + r4 * 4);
        Zs[(r4 * 4 + 0) * RPITCH + d] = v.x;
        Zs[(r4 * 4 + 1) * RPITCH + d] = v.y;
        Zs[(r4 * 4 + 2) * RPITCH + d] = v.z;
        Zs[(r4 * 4 + 3) * RPITCH + d] = v.w;
    }
    __syncthreads();
    if (tid < 128) {
        float s = 0.f;
#pragma unroll 8
        for (int d = 0; d < DIMS; ++d)
            s = __fadd_rn(s, __fmul_rn(Zs[tid * RPITCH + d], Zs[tid * RPITCH + d]));
        z2s[tid] = s;
    }
    __syncthreads();

    // warp w handles rows w*16 .. w*16+15
    for (int rr = 0; rr < 16; ++rr) {
        const int r = w * 16 + rr;
        const int n = n0 + r;
        const float* zr = Zs + r * RPITCH;
        float bestd = 3.4e38f; int besti = 0x7fffffff;
        if (!g_flag[n]) {
#pragma unroll
            for (int q = 0; q < NC; ++q) {
                int cand = g_cand[n * NC + q];
                float4 za = *reinterpret_cast<const float4*>(zr + lane * 8);
                float4 zc = *reinterpret_cast<const float4*>(zr + lane * 8 + 4);
                float4 ca = *reinterpret_cast<const float4*>(cb + (size_t)cand * 256 + lane * 8);
                float4 cc = *reinterpret_cast<const float4*>(cb + (size_t)cand * 256 + lane * 8 + 4);
                float s = 0.f;
                s = __fmaf_rn(za.x, ca.x, s); s = __fmaf_rn(za.y, ca.y, s);
                s = __fmaf_rn(za.z, ca.z, s); s = __fmaf_rn(za.w, ca.w, s);
                s = __fmaf_rn(zc.x, cc.x, s); s = __fmaf_rn(zc.y, cc.y, s);
                s = __fmaf_rn(zc.z, cc.z, s); s = __fmaf_rn(zc.w, cc.w, s);
#pragma unroll
                for (int o = 16; o > 0; o >>= 1)
                    s += __shfl_down_sync(0xffffffffu, s, o);
                s = __shfl_sync(0xffffffffu, s, 0);
                float dist = __fsub_rn(__fadd_rn(z2s[r], g_c2[cand]),
                                       __fmul_rn(2.0f, s));
                if (dist < bestd || (dist == bestd && cand < besti)) {
                    bestd = dist; besti = cand;
                }
            }
            if (lane == 0) idxs[r] = besti;
        } else {
            // exact full scan fallback (rare)
            for (int kk = lane; kk < NUM_K; kk += 32) {
                const float* cr = cb + (size_t)kk * 256;
                float s = 0.f;
#pragma unroll 8
                for (int d = 0; d < DIMS; ++d) s = __fmaf_rn(zr[d], cr[d], s);
                float dist = __fsub_rn(__fadd_rn(z2s[r], g_c2[kk]),
                                       __fmul_rn(2.0f, s));
                if (dist < bestd || (dist == bestd && kk < besti)) {
                    bestd = dist; besti = kk;
                }
            }
#pragma unroll
            for (int o = 16; o > 0; o >>= 1) {
                float d2 = __shfl_down_sync(0xffffffffu, bestd, o);
                int   i2 = __shfl_down_sync(0xffffffffu, besti, o);
                if (d2 < bestd || (d2 == bestd && i2 < besti)) {
                    bestd = d2; besti = i2;
                }
            }
            if (lane == 0) idxs[r] = besti;
        }
    }
    __syncthreads();

    // output q = fl(z + fl(c - z)) + fp64 loss partial
    double ls = 0.0;
    for (int i = tid; i < 8192; i += 256) {
        int d = i >> 5, r4 = i & 31;
        float4 zv = make_float4(Zs[(r4 * 4 + 0) * RPITCH + d],
                                Zs[(r4 * 4 + 1) * RPITCH + d],
                                Zs[(r4 * 4 + 2) * RPITCH + d],
                                Zs[(r4 * 4 + 3) * RPITCH + d]);
        int i0 = idxs[r4 * 4 + 0], i1 = idxs[r4 * 4 + 1];
        int i2 = idxs[r4 * 4 + 2], i3 = idxs[r4 * 4 + 3];
        float c0 = cb[(size_t)i0 * DIMS + d];
        float c1 = cb[(size_t)i1 * DIMS + d];
        float c2 = cb[(size_t)i2 * DIMS + d];
        float c3 = cb[(size_t)i3 * DIMS + d];
        float e0 = __fsub_rn(c0, zv.x), e1 = __fsub_rn(c1, zv.y);
        float e2 = __fsub_rn(c2, zv.z), e3 = __fsub_rn(c3, zv.w);
        float4 qv = make_float4(__fadd_rn(zv.x, e0), __fadd_rn(zv.y, e1),
                                __fadd_rn(zv.z, e2), __fadd_rn(zv.w, e3));
        ls += (double)e0 * e0 + (double)e1 * e1
            + (double)e2 * e2 + (double)e3 * e3;
        *reinterpret_cast<float4*>(outb + (size_t)d * 1024 + r4 * 4) = qv;
    }
#pragma unroll
    for (int o = 16; o > 0; o >>= 1)
        ls += __shfl_down_sync(0xffffffffu, ls, o);
    if (lane == 0) lred[w] = ls;
    __syncthreads();
    if (tid == 0) {
        double s = 0.0;
#pragma unroll
        for (int q = 0; q < 8; ++q) s += lred[q];
        g_partial[blockIdx.x] = s;
    }
}

// ============================================================================
// Kernel 4: finalize losses
// ============================================================================
__global__ void vq_final(float* __restrict__ out, int out_size) {
    __shared__ double sp[4];
    int t = threadIdx.x;
    double v = g_partial[t];
#pragma unroll
    for (int o = 16; o > 0; o >>= 1)
        v += __shfl_down_sync(0xffffffffu, v, o);
    if ((t & 31) == 0) sp[t >> 5] = v;
    __syncthreads();
    if (t == 0) {
        double s = sp[0] + sp[1] + sp[2] + sp[3];
        double mse = s / (double)Q_ELEMS;
        if (out_size >= Q_ELEMS + 3) {
            out[Q_ELEMS + 0] = (float)(mse * 1.25);
            out[Q_ELEMS + 1] = (float)mse;
            out[Q_ELEMS + 2] = (float)mse;
        }
    }
}

extern "C" void kernel_launch(void* const* d_in, const int* in_sizes, int n_in,
                              void* d_out, int out_size) {
    (void)in_sizes; (void)n_in;
    const float* z  = (const float*)d_in[0];
    const float* cb = (const float*)d_in[1];
    float* out = (float*)d_out;

    cudaFuncSetAttribute(vq_gemm, cudaFuncAttributeMaxDynamicSharedMemorySize,
                         SMEM_GEMM);
    cudaFuncSetAttribute(vq_rescore, cudaFuncAttributeMaxDynamicSharedMemorySize,
                         SMEM_RES);

    vq_prep<<<256, 256>>>(cb);
    vq_gemm<<<128, 256, SMEM_GEMM>>>(z);
    vq_rescore<<<128, 256, SMEM_RES>>>(z, cb, out);
    vq_final<<<1, 128>>>(out, out_size);
}